// round 13
// baseline (speedup 1.0000x reference)
#include <cuda_runtime.h>
#include <cuda_fp16.h>
#include <mma.h>
#include <stdint.h>

using namespace nvcuda;

#define N_NODES 100000
#define N_EDGES 1600000
#define N_GRAPHS 256
#define SCAN_BLOCKS 100
#define SCAN_CHUNK 1000   // N_NODES = SCAN_BLOCKS * SCAN_CHUNK exactly

// ---------------- scratch (no allocation allowed -> device globals) ----------
__device__ int    g_deg_out[N_NODES];
__device__ int    g_deg_in[N_NODES];
__device__ float  g_norm_src[N_NODES];
__device__ float  g_norm_dst[N_NODES];
__device__ int    g_row[N_NODES + 1];           // CSR row offsets (by dst)
__device__ int    g_cur[N_NODES];               // fill cursors
__device__ int    g_csr[N_EDGES];               // src index per CSR slot
__device__ int    g_blk[SCAN_BLOCKS];           // per-block degree sums
__device__ __half g_hA[(size_t)N_NODES * 128];  // fp16 feature buffer A
__device__ __half g_hB[(size_t)N_NODES * 128];  // fp16 feature buffer B
__device__ __half g_w1h[64 * 128];              // fp16 weights
__device__ __half g_w2h[128 * 128];
__device__ __half g_w3h[128 * 64];
__device__ int    g_flag_idx;                   // 1 = src/dst are int32
__device__ int    g_flag_gid;                   // 1 = graph_id is int32

// ---------------- helpers ----------------------------------------------------
__device__ __forceinline__ int load_idx(const void* p, long long i, int is32) {
    if (is32) return ((const int*)p)[i];
    return (int)(((const long long*)p)[i]);
}

// init: zero degrees + output; block 0 additionally does dtype detection.
// int64 values < 2^31 -> every odd 32-bit word is 0; int32 data -> nonzero.
// src: head window (random values => certain nonzero if int32).
// gid: TAIL window (sorted ascending; head is legitimately zero either way).
__global__ void init_kernel(const unsigned* __restrict__ s,
                            const unsigned* __restrict__ g,
                            float* __restrict__ out) {
    int i = blockIdx.x * blockDim.x + threadIdx.x;
    if (i == 0) { g_flag_idx = 0; g_flag_gid = 0; }
    if (i < N_NODES) { g_deg_out[i] = 0; g_deg_in[i] = 0; }
    if (i < N_GRAPHS * 64) out[i] = 0.0f;
    if (blockIdx.x == 0) {
        int fi = 0, fg = 0;
        for (int j = threadIdx.x; j < 2048; j += 256)
            if ((j & 1) && s[j]) fi = 1;
        for (int j = N_NODES - 2048 + threadIdx.x; j < N_NODES; j += 256)
            if ((j & 1) && g[j]) fg = 1;
        if (fi) g_flag_idx = 1;
        if (fg) g_flag_gid = 1;
    }
}

// convert all three weight matrices to fp16 once
__global__ void wconv_kernel(const float* __restrict__ W1,
                             const float* __restrict__ W2,
                             const float* __restrict__ W3) {
    int i = blockIdx.x * blockDim.x + threadIdx.x;
    if (i < 64 * 128)  g_w1h[i] = __float2half_rn(W1[i]);
    if (i < 128 * 128) g_w2h[i] = __float2half_rn(W2[i]);
    if (i < 128 * 64)  g_w3h[i] = __float2half_rn(W3[i]);
}

// ---------------- degrees ----------------------------------------------------
__global__ void deg_kernel(const void* src, const void* dst) {
    int is32 = g_flag_idx;
    long long i = (long long)blockIdx.x * blockDim.x + threadIdx.x;
    long long stride = (long long)gridDim.x * blockDim.x;
    for (; i < N_EDGES; i += stride) {
        atomicAdd(&g_deg_out[load_idx(src, i, is32)], 1);
        atomicAdd(&g_deg_in[load_idx(dst, i, is32)], 1);
    }
}

// scan stage A: per-block degree sums + norms (SCAN_BLOCKS blocks, 1024 thr)
__global__ void scanA_kernel() {
    __shared__ int ssum[1024];
    int b = blockIdx.x;
    int t = threadIdx.x;
    int i = b * SCAN_CHUNK + t;
    int d = 0;
    if (t < SCAN_CHUNK) {
        d = g_deg_in[i];
        int doo = g_deg_out[i];
        g_norm_src[i] = (doo > 0) ? rsqrtf((float)doo) : 0.0f;
        g_norm_dst[i] = (d   > 0) ? rsqrtf((float)d)   : 0.0f;
    }
    ssum[t] = d;
    __syncthreads();
    for (int off = 512; off > 0; off >>= 1) {
        if (t < off) ssum[t] += ssum[t + off];
        __syncthreads();
    }
    if (t == 0) g_blk[b] = ssum[0];
}

// scan stage B: every block scans the 100 partials + its local 1000 elements
__global__ void scanB_kernel() {
    __shared__ int sblk[128];
    __shared__ int sdeg[1024];
    int b = blockIdx.x;
    int t = threadIdx.x;

    if (t < 128) sblk[t] = (t < SCAN_BLOCKS) ? g_blk[t] : 0;
    __syncthreads();
    for (int off = 1; off < 128; off <<= 1) {
        int v = (t >= off && t < 128) ? sblk[t - off] : 0;
        __syncthreads();
        if (t < 128) sblk[t] += v;
        __syncthreads();
    }
    int blk_off = (b > 0) ? sblk[b - 1] : 0;

    int i = b * SCAN_CHUNK + t;
    int d = (t < SCAN_CHUNK) ? g_deg_in[i] : 0;
    sdeg[t] = d;
    __syncthreads();
    for (int off = 1; off < 1024; off <<= 1) {
        int v = (t >= off) ? sdeg[t - off] : 0;
        __syncthreads();
        sdeg[t] += v;
        __syncthreads();
    }
    if (t < SCAN_CHUNK) {
        int excl = blk_off + sdeg[t] - d;
        g_row[i] = excl;
        g_cur[i] = excl;
        if (b == SCAN_BLOCKS - 1 && t == SCAN_CHUNK - 1)
            g_row[N_NODES] = blk_off + sdeg[t];
    }
}

__global__ void fill_csr_kernel(const void* src, const void* dst) {
    int is32 = g_flag_idx;
    long long i = (long long)blockIdx.x * blockDim.x + threadIdx.x;
    long long stride = (long long)gridDim.x * blockDim.x;
    for (; i < N_EDGES; i += stride) {
        int d = load_idx(dst, i, is32);
        int pos = atomicAdd(&g_cur[d], 1);
        g_csr[pos] = load_idx(src, i, is32);
    }
}

// ------ prescale: g_hA = fp16(h * norm_src), row-major 64/node ---------------
__global__ void prescale_kernel(const float* __restrict__ h) {
    int i = blockIdx.x * blockDim.x + threadIdx.x;   // over N_NODES*32 half2
    if (i >= N_NODES * 32) return;
    int n = i >> 5;
    float ns = g_norm_src[n];
    float2 v = ((const float2*)h)[i];
    v.x *= ns; v.y *= ns;
    ((__half2*)g_hA)[i] = __float22half2_rn(v);
}

// ------- CSR gather (64-dim fp16), QUARTER-WARP (8 lanes) per node -----------
// 8 lanes x uint4 (16B) = 128B row; 4 nodes per warp concurrently.
__global__ void gather64h_kernel(const __half* __restrict__ x,
                                 __half* __restrict__ out) {
    int gid  = blockIdx.x * blockDim.x + threadIdx.x;
    int node = gid >> 3;
    int lane = gid & 7;
    if (node >= N_NODES) return;
    int lo = g_row[node], hi = g_row[node + 1];
    float a[8] = {0,0,0,0,0,0,0,0};
    float b[8] = {0,0,0,0,0,0,0,0};
    int j = lo;
    for (; j + 1 < hi; j += 2) {
        int s0 = g_csr[j], s1 = g_csr[j + 1];
        uint4 u0 = ((const uint4*)(x + (size_t)s0 * 64))[lane];
        uint4 u1 = ((const uint4*)(x + (size_t)s1 * 64))[lane];
        float2 p0 = __half22float2(*(__half2*)&u0.x);
        float2 p1 = __half22float2(*(__half2*)&u0.y);
        float2 p2 = __half22float2(*(__half2*)&u0.z);
        float2 p3 = __half22float2(*(__half2*)&u0.w);
        float2 q0 = __half22float2(*(__half2*)&u1.x);
        float2 q1 = __half22float2(*(__half2*)&u1.y);
        float2 q2 = __half22float2(*(__half2*)&u1.z);
        float2 q3 = __half22float2(*(__half2*)&u1.w);
        a[0] += p0.x; a[1] += p0.y; a[2] += p1.x; a[3] += p1.y;
        a[4] += p2.x; a[5] += p2.y; a[6] += p3.x; a[7] += p3.y;
        b[0] += q0.x; b[1] += q0.y; b[2] += q1.x; b[3] += q1.y;
        b[4] += q2.x; b[5] += q2.y; b[6] += q3.x; b[7] += q3.y;
    }
    if (j < hi) {
        int s0 = g_csr[j];
        uint4 u0 = ((const uint4*)(x + (size_t)s0 * 64))[lane];
        float2 p0 = __half22float2(*(__half2*)&u0.x);
        float2 p1 = __half22float2(*(__half2*)&u0.y);
        float2 p2 = __half22float2(*(__half2*)&u0.z);
        float2 p3 = __half22float2(*(__half2*)&u0.w);
        a[0] += p0.x; a[1] += p0.y; a[2] += p1.x; a[3] += p1.y;
        a[4] += p2.x; a[5] += p2.y; a[6] += p3.x; a[7] += p3.y;
    }
    float nd = g_norm_dst[node];
    __half2 r0 = __float22half2_rn(make_float2((a[0]+b[0])*nd, (a[1]+b[1])*nd));
    __half2 r1 = __float22half2_rn(make_float2((a[2]+b[2])*nd, (a[3]+b[3])*nd));
    __half2 r2 = __float22half2_rn(make_float2((a[4]+b[4])*nd, (a[5]+b[5])*nd));
    __half2 r3 = __float22half2_rn(make_float2((a[6]+b[6])*nd, (a[7]+b[7])*nd));
    uint4 o;
    o.x = *(unsigned*)&r0; o.y = *(unsigned*)&r1;
    o.z = *(unsigned*)&r2; o.w = *(unsigned*)&r3;
    ((uint4*)(out + (size_t)node * 64))[lane] = o;
}

// ------- CSR gather (128-dim fp16), QUARTER-WARP per node --------------------
// 8 lanes x 2 uint4 slices (lane, lane+8) = 256B row; 4 nodes per warp.
__global__ void gather128h_kernel(const __half* __restrict__ x,
                                  __half* __restrict__ out) {
    int gid  = blockIdx.x * blockDim.x + threadIdx.x;
    int node = gid >> 3;
    int lane = gid & 7;
    if (node >= N_NODES) return;
    int lo = g_row[node], hi = g_row[node + 1];
    float a[16];
#pragma unroll
    for (int k = 0; k < 16; k++) a[k] = 0.0f;
    for (int j = lo; j < hi; j++) {
        int s0 = g_csr[j];
        const uint4* row = (const uint4*)(x + (size_t)s0 * 128);
        uint4 u0 = row[lane];
        uint4 u1 = row[lane + 8];
        float2 p0 = __half22float2(*(__half2*)&u0.x);
        float2 p1 = __half22float2(*(__half2*)&u0.y);
        float2 p2 = __half22float2(*(__half2*)&u0.z);
        float2 p3 = __half22float2(*(__half2*)&u0.w);
        float2 q0 = __half22float2(*(__half2*)&u1.x);
        float2 q1 = __half22float2(*(__half2*)&u1.y);
        float2 q2 = __half22float2(*(__half2*)&u1.z);
        float2 q3 = __half22float2(*(__half2*)&u1.w);
        a[0] += p0.x; a[1] += p0.y; a[2]  += p1.x; a[3]  += p1.y;
        a[4] += p2.x; a[5] += p2.y; a[6]  += p3.x; a[7]  += p3.y;
        a[8] += q0.x; a[9] += q0.y; a[10] += q1.x; a[11] += q1.y;
        a[12]+= q2.x; a[13]+= q2.y; a[14] += q3.x; a[15] += q3.y;
    }
    float nd = g_norm_dst[node];
    __half2 r[8];
#pragma unroll
    for (int k = 0; k < 8; k++)
        r[k] = __float22half2_rn(make_float2(a[2*k] * nd, a[2*k+1] * nd));
    uint4 o0, o1;
    o0.x = *(unsigned*)&r[0]; o0.y = *(unsigned*)&r[1];
    o0.z = *(unsigned*)&r[2]; o0.w = *(unsigned*)&r[3];
    o1.x = *(unsigned*)&r[4]; o1.y = *(unsigned*)&r[5];
    o1.z = *(unsigned*)&r[6]; o1.w = *(unsigned*)&r[7];
    uint4* orow = (uint4*)(out + (size_t)node * 128);
    orow[lane]     = o0;
    orow[lane + 8] = o1;
}

// final layer gather (64-dim fp16), QUARTER-WARP per node, pooled atomicAdd ---
__global__ void gather_pool_kernel(const __half* __restrict__ x,
                                   const float* __restrict__ b3,
                                   const void* __restrict__ gid,
                                   float* __restrict__ out) {
    int g_id = blockIdx.x * blockDim.x + threadIdx.x;
    int node = g_id >> 3;
    int lane = g_id & 7;
    if (node >= N_NODES) return;
    int lo = g_row[node], hi = g_row[node + 1];
    float a[8] = {0,0,0,0,0,0,0,0};
    float b[8] = {0,0,0,0,0,0,0,0};
    int j = lo;
    for (; j + 1 < hi; j += 2) {
        int s0 = g_csr[j], s1 = g_csr[j + 1];
        uint4 u0 = ((const uint4*)(x + (size_t)s0 * 64))[lane];
        uint4 u1 = ((const uint4*)(x + (size_t)s1 * 64))[lane];
        float2 p0 = __half22float2(*(__half2*)&u0.x);
        float2 p1 = __half22float2(*(__half2*)&u0.y);
        float2 p2 = __half22float2(*(__half2*)&u0.z);
        float2 p3 = __half22float2(*(__half2*)&u0.w);
        float2 q0 = __half22float2(*(__half2*)&u1.x);
        float2 q1 = __half22float2(*(__half2*)&u1.y);
        float2 q2 = __half22float2(*(__half2*)&u1.z);
        float2 q3 = __half22float2(*(__half2*)&u1.w);
        a[0] += p0.x; a[1] += p0.y; a[2] += p1.x; a[3] += p1.y;
        a[4] += p2.x; a[5] += p2.y; a[6] += p3.x; a[7] += p3.y;
        b[0] += q0.x; b[1] += q0.y; b[2] += q1.x; b[3] += q1.y;
        b[4] += q2.x; b[5] += q2.y; b[6] += q3.x; b[7] += q3.y;
    }
    if (j < hi) {
        int s0 = g_csr[j];
        uint4 u0 = ((const uint4*)(x + (size_t)s0 * 64))[lane];
        float2 p0 = __half22float2(*(__half2*)&u0.x);
        float2 p1 = __half22float2(*(__half2*)&u0.y);
        float2 p2 = __half22float2(*(__half2*)&u0.z);
        float2 p3 = __half22float2(*(__half2*)&u0.w);
        a[0] += p0.x; a[1] += p0.y; a[2] += p1.x; a[3] += p1.y;
        a[4] += p2.x; a[5] += p2.y; a[6] += p3.x; a[7] += p3.y;
    }
    float nd = g_norm_dst[node];
    float4 bb0 = ((const float4*)b3)[lane * 2];
    float4 bb1 = ((const float4*)b3)[lane * 2 + 1];
    int g = load_idx(gid, node, g_flag_gid);
    float* o = out + (size_t)g * 64 + lane * 8;
    atomicAdd(o + 0, fmaxf(fmaf(a[0] + b[0], nd, bb0.x), 0.0f));
    atomicAdd(o + 1, fmaxf(fmaf(a[1] + b[1], nd, bb0.y), 0.0f));
    atomicAdd(o + 2, fmaxf(fmaf(a[2] + b[2], nd, bb0.z), 0.0f));
    atomicAdd(o + 3, fmaxf(fmaf(a[3] + b[3], nd, bb0.w), 0.0f));
    atomicAdd(o + 4, fmaxf(fmaf(a[4] + b[4], nd, bb1.x), 0.0f));
    atomicAdd(o + 5, fmaxf(fmaf(a[5] + b[5], nd, bb1.y), 0.0f));
    atomicAdd(o + 6, fmaxf(fmaf(a[6] + b[6], nd, bb1.z), 0.0f));
    atomicAdd(o + 7, fmaxf(fmaf(a[7] + b[7], nd, bb1.w), 0.0f));
}

// ------- tensor-core GEMM with smem-staged A tile ----------------------------
// A: [N_NODES, DIN] fp16 row-major.  Bh: [DIN, DOUT] fp16 row-major.
// M_TILE=80, warps = DOUT/16, each warp owns one 16-col n_tile and 5 m-frags.
// EPI==1: v = relu(acc + bias[col]) * norm_src[row];  EPI==0: v = acc.
template <int DIN, int DOUT, int EPI>
__global__ void wmma_gemm_kernel(const __half* __restrict__ A,
                                 const __half* __restrict__ Bh,
                                 const float* __restrict__ bias,
                                 __half* __restrict__ out) {
    constexpr int M_TILE  = 80;
    constexpr int NWARPS  = DOUT / 16;
    constexpr int THREADS = NWARPS * 32;
    constexpr int MF      = M_TILE / 16;    // 5 m-fragments per warp
    __shared__ __half As[M_TILE * DIN];
    __shared__ float scratch[NWARPS][16 * 16];
    int tid  = threadIdx.x;
    int w    = tid >> 5;
    int lane = tid & 31;
    size_t base = (size_t)blockIdx.x * M_TILE;

    // cooperative 16B-vector load of the A tile
    {
        const uint4* srcv = (const uint4*)(A + base * DIN);
        uint4* dstv = (uint4*)As;
#pragma unroll
        for (int i = tid; i < M_TILE * DIN / 8; i += THREADS) dstv[i] = srcv[i];
    }
    __syncthreads();

    wmma::fragment<wmma::accumulator, 16, 16, 16, float> acc[MF];
#pragma unroll
    for (int m = 0; m < MF; m++) wmma::fill_fragment(acc[m], 0.0f);

    wmma::fragment<wmma::matrix_a, 16, 16, 16, __half, wmma::row_major> afrag;
    wmma::fragment<wmma::matrix_b, 16, 16, 16, __half, wmma::row_major> bfrag;

#pragma unroll
    for (int k = 0; k < DIN / 16; k++) {
        wmma::load_matrix_sync(bfrag, Bh + (size_t)(k * 16) * DOUT + w * 16, DOUT);
#pragma unroll
        for (int m = 0; m < MF; m++) {
            wmma::load_matrix_sync(afrag, As + (size_t)(m * 16) * DIN + k * 16, DIN);
            wmma::mma_sync(acc[m], afrag, bfrag, acc[m]);
        }
    }

#pragma unroll
    for (int m = 0; m < MF; m++) {
        wmma::store_matrix_sync(scratch[w], acc[m], 16, wmma::mem_row_major);
        __syncwarp();
#pragma unroll
        for (int e = lane; e < 256; e += 32) {
            int r = e >> 4, c = e & 15;
            size_t row = base + (size_t)m * 16 + r;
            int col = w * 16 + c;
            float v = scratch[w][e];
            if (EPI) v = fmaxf(v + bias[col], 0.0f) * g_norm_src[row];
            out[row * DOUT + col] = __float2half_rn(v);
        }
        __syncwarp();
    }
}

// ---------------- launch ------------------------------------------------------
extern "C" void kernel_launch(void* const* d_in, const int* in_sizes, int n_in,
                              void* d_out, int out_size) {
    const float* h        = (const float*)d_in[0];
    const void*  src      = d_in[1];
    const void*  dst      = d_in[2];
    const void*  graph_id = d_in[3];
    const float* W1 = (const float*)d_in[4];
    const float* b1 = (const float*)d_in[5];
    const float* W2 = (const float*)d_in[6];
    const float* b2 = (const float*)d_in[7];
    const float* W3 = (const float*)d_in[8];
    const float* b3 = (const float*)d_in[9];
    float* out = (float*)d_out;

    __half *pA, *pB, *pW1, *pW2, *pW3;
    cudaGetSymbolAddress((void**)&pA,  g_hA);
    cudaGetSymbolAddress((void**)&pB,  g_hB);
    cudaGetSymbolAddress((void**)&pW1, g_w1h);
    cudaGetSymbolAddress((void**)&pW2, g_w2h);
    cudaGetSymbolAddress((void**)&pW3, g_w3h);

    // setup: init (+detect, +zero out), degrees, 2-stage scan, CSR fill, W->fp16
    init_kernel<<<(N_NODES + 255) / 256, 256>>>((const unsigned*)src,
                                                (const unsigned*)graph_id, out);
    deg_kernel<<<2048, 256>>>(src, dst);
    scanA_kernel<<<SCAN_BLOCKS, 1024>>>();
    scanB_kernel<<<SCAN_BLOCKS, 1024>>>();
    fill_csr_kernel<<<2048, 256>>>(src, dst);
    wconv_kernel<<<(128 * 128 + 255) / 256, 256>>>(W1, W2, W3);

    const int QW_GRID = (N_NODES * 8 + 255) / 256;    // quarter-warp per node

    // layer 1: prescale(h)->A(64), gather64 A->B(64), wmma 64->128 B->A
    prescale_kernel<<<(N_NODES * 32 + 255) / 256, 256>>>(h);
    gather64h_kernel<<<QW_GRID, 256>>>(pA, pB);
    wmma_gemm_kernel<64, 128, 1><<<N_NODES / 80, 256>>>(pB, pW1, b1, pA);

    // layer 2: gather128 A->B, wmma 128->128 B->A
    gather128h_kernel<<<QW_GRID, 256>>>(pA, pB);
    wmma_gemm_kernel<128, 128, 1><<<N_NODES / 80, 256>>>(pB, pW2, b2, pA);

    // layer 3: transform first (wmma 128->64, no epi) A->B, then gather+pool
    wmma_gemm_kernel<128, 64, 0><<<N_NODES / 80, 128>>>(pA, pW3, nullptr, pB);
    gather_pool_kernel<<<QW_GRID, 256>>>(pB, b3, graph_id, out);
}

// round 14
// speedup vs baseline: 1.0698x; 1.0698x over previous
#include <cuda_runtime.h>
#include <cuda_fp16.h>
#include <mma.h>
#include <stdint.h>

using namespace nvcuda;

#define N_NODES 100000
#define N_EDGES 1600000
#define N_GRAPHS 256
#define SCAN_BLOCKS 100
#define SCAN_CHUNK 1000   // N_NODES = SCAN_BLOCKS * SCAN_CHUNK exactly

// ---------------- scratch (no allocation allowed -> device globals) ----------
__device__ int    g_deg_out[N_NODES];
__device__ int    g_deg_in[N_NODES];
__device__ float  g_norm_src[N_NODES];
__device__ float  g_norm_dst[N_NODES];
__device__ int    g_row[N_NODES + 1];           // CSR row offsets (by dst)
__device__ int    g_cur[N_NODES];               // fill cursors
__device__ int    g_csr[N_EDGES];               // src index per CSR slot
__device__ int    g_blk[SCAN_BLOCKS];           // per-block degree sums
__device__ __half g_hA[(size_t)N_NODES * 128];  // fp16 feature buffer A
__device__ __half g_hB[(size_t)N_NODES * 128];  // fp16 feature buffer B
__device__ __half g_w1h[64 * 128];              // fp16 weights
__device__ __half g_w2h[128 * 128];
__device__ __half g_w3h[128 * 64];
__device__ int    g_flag_idx;                   // 1 = src/dst are int32
__device__ int    g_flag_gid;                   // 1 = graph_id is int32

// ---------------- helpers ----------------------------------------------------
__device__ __forceinline__ int load_idx(const void* p, long long i, int is32) {
    if (is32) return ((const int*)p)[i];
    return (int)(((const long long*)p)[i]);
}

// init: zero degrees + output; block 0 additionally does dtype detection.
// int64 values < 2^31 -> every odd 32-bit word is 0; int32 data -> nonzero.
// src: head window (random values => certain nonzero if int32).
// gid: TAIL window (sorted ascending; head is legitimately zero either way).
__global__ void init_kernel(const unsigned* __restrict__ s,
                            const unsigned* __restrict__ g,
                            float* __restrict__ out) {
    int i = blockIdx.x * blockDim.x + threadIdx.x;
    if (i == 0) { g_flag_idx = 0; g_flag_gid = 0; }
    if (i < N_NODES) { g_deg_out[i] = 0; g_deg_in[i] = 0; }
    if (i < N_GRAPHS * 64) out[i] = 0.0f;
    if (blockIdx.x == 0) {
        int fi = 0, fg = 0;
        for (int j = threadIdx.x; j < 2048; j += 256)
            if ((j & 1) && s[j]) fi = 1;
        for (int j = N_NODES - 2048 + threadIdx.x; j < N_NODES; j += 256)
            if ((j & 1) && g[j]) fg = 1;
        if (fi) g_flag_idx = 1;
        if (fg) g_flag_gid = 1;
    }
}

// convert all three weight matrices to fp16 once
__global__ void wconv_kernel(const float* __restrict__ W1,
                             const float* __restrict__ W2,
                             const float* __restrict__ W3) {
    int i = blockIdx.x * blockDim.x + threadIdx.x;
    if (i < 64 * 128)  g_w1h[i] = __float2half_rn(W1[i]);
    if (i < 128 * 128) g_w2h[i] = __float2half_rn(W2[i]);
    if (i < 128 * 64)  g_w3h[i] = __float2half_rn(W3[i]);
}

// ---------------- degrees ----------------------------------------------------
__global__ void deg_kernel(const void* src, const void* dst) {
    int is32 = g_flag_idx;
    long long i = (long long)blockIdx.x * blockDim.x + threadIdx.x;
    long long stride = (long long)gridDim.x * blockDim.x;
    for (; i < N_EDGES; i += stride) {
        atomicAdd(&g_deg_out[load_idx(src, i, is32)], 1);
        atomicAdd(&g_deg_in[load_idx(dst, i, is32)], 1);
    }
}

// scan stage A: per-block degree sums + norms (SCAN_BLOCKS blocks, 1024 thr)
__global__ void scanA_kernel() {
    __shared__ int ssum[1024];
    int b = blockIdx.x;
    int t = threadIdx.x;
    int i = b * SCAN_CHUNK + t;
    int d = 0;
    if (t < SCAN_CHUNK) {
        d = g_deg_in[i];
        int doo = g_deg_out[i];
        g_norm_src[i] = (doo > 0) ? rsqrtf((float)doo) : 0.0f;
        g_norm_dst[i] = (d   > 0) ? rsqrtf((float)d)   : 0.0f;
    }
    ssum[t] = d;
    __syncthreads();
    for (int off = 512; off > 0; off >>= 1) {
        if (t < off) ssum[t] += ssum[t + off];
        __syncthreads();
    }
    if (t == 0) g_blk[b] = ssum[0];
}

// scan stage B: every block scans the 100 partials + its local 1000 elements
__global__ void scanB_kernel() {
    __shared__ int sblk[128];
    __shared__ int sdeg[1024];
    int b = blockIdx.x;
    int t = threadIdx.x;

    if (t < 128) sblk[t] = (t < SCAN_BLOCKS) ? g_blk[t] : 0;
    __syncthreads();
    for (int off = 1; off < 128; off <<= 1) {
        int v = (t >= off && t < 128) ? sblk[t - off] : 0;
        __syncthreads();
        if (t < 128) sblk[t] += v;
        __syncthreads();
    }
    int blk_off = (b > 0) ? sblk[b - 1] : 0;

    int i = b * SCAN_CHUNK + t;
    int d = (t < SCAN_CHUNK) ? g_deg_in[i] : 0;
    sdeg[t] = d;
    __syncthreads();
    for (int off = 1; off < 1024; off <<= 1) {
        int v = (t >= off) ? sdeg[t - off] : 0;
        __syncthreads();
        sdeg[t] += v;
        __syncthreads();
    }
    if (t < SCAN_CHUNK) {
        int excl = blk_off + sdeg[t] - d;
        g_row[i] = excl;
        g_cur[i] = excl;
        if (b == SCAN_BLOCKS - 1 && t == SCAN_CHUNK - 1)
            g_row[N_NODES] = blk_off + sdeg[t];
    }
}

__global__ void fill_csr_kernel(const void* src, const void* dst) {
    int is32 = g_flag_idx;
    long long i = (long long)blockIdx.x * blockDim.x + threadIdx.x;
    long long stride = (long long)gridDim.x * blockDim.x;
    for (; i < N_EDGES; i += stride) {
        int d = load_idx(dst, i, is32);
        int pos = atomicAdd(&g_cur[d], 1);
        g_csr[pos] = load_idx(src, i, is32);
    }
}

// ------ prescale: g_hA = fp16(h * norm_src), row-major 64/node ---------------
__global__ void prescale_kernel(const float* __restrict__ h) {
    int i = blockIdx.x * blockDim.x + threadIdx.x;   // over N_NODES*32 half2
    if (i >= N_NODES * 32) return;
    int n = i >> 5;
    float ns = g_norm_src[n];
    float2 v = ((const float2*)h)[i];
    v.x *= ns; v.y *= ns;
    ((__half2*)g_hA)[i] = __float22half2_rn(v);
}

// ------- CSR gather (64-dim fp16), HALF-WARP per node, 4-edge pipelined ------
// 16 lanes x uint2 (8B) = 128B row; 2 nodes per warp, 4 rows in flight.
__global__ void gather64h_kernel(const __half* __restrict__ x,
                                 __half* __restrict__ out) {
    int gid  = blockIdx.x * blockDim.x + threadIdx.x;
    int node = gid >> 4;
    int lane = gid & 15;
    if (node >= N_NODES) return;
    int lo = g_row[node], hi = g_row[node + 1];
    float a[4] = {0,0,0,0};
    float b[4] = {0,0,0,0};
    float c[4] = {0,0,0,0};
    float d[4] = {0,0,0,0};
    int j = lo;
    for (; j + 3 < hi; j += 4) {
        int s0 = g_csr[j], s1 = g_csr[j + 1], s2 = g_csr[j + 2], s3 = g_csr[j + 3];
        uint2 u0 = ((const uint2*)(x + (size_t)s0 * 64))[lane];
        uint2 u1 = ((const uint2*)(x + (size_t)s1 * 64))[lane];
        uint2 u2 = ((const uint2*)(x + (size_t)s2 * 64))[lane];
        uint2 u3 = ((const uint2*)(x + (size_t)s3 * 64))[lane];
        float2 p0 = __half22float2(*(__half2*)&u0.x);
        float2 p1 = __half22float2(*(__half2*)&u0.y);
        float2 q0 = __half22float2(*(__half2*)&u1.x);
        float2 q1 = __half22float2(*(__half2*)&u1.y);
        float2 r0 = __half22float2(*(__half2*)&u2.x);
        float2 r1 = __half22float2(*(__half2*)&u2.y);
        float2 t0 = __half22float2(*(__half2*)&u3.x);
        float2 t1 = __half22float2(*(__half2*)&u3.y);
        a[0] += p0.x; a[1] += p0.y; a[2] += p1.x; a[3] += p1.y;
        b[0] += q0.x; b[1] += q0.y; b[2] += q1.x; b[3] += q1.y;
        c[0] += r0.x; c[1] += r0.y; c[2] += r1.x; c[3] += r1.y;
        d[0] += t0.x; d[1] += t0.y; d[2] += t1.x; d[3] += t1.y;
    }
    for (; j < hi; j++) {
        int s0 = g_csr[j];
        uint2 u0 = ((const uint2*)(x + (size_t)s0 * 64))[lane];
        float2 p0 = __half22float2(*(__half2*)&u0.x);
        float2 p1 = __half22float2(*(__half2*)&u0.y);
        a[0] += p0.x; a[1] += p0.y; a[2] += p1.x; a[3] += p1.y;
    }
    float nd = g_norm_dst[node];
    __half2 r0 = __float22half2_rn(make_float2(((a[0]+b[0])+(c[0]+d[0]))*nd,
                                               ((a[1]+b[1])+(c[1]+d[1]))*nd));
    __half2 r1 = __float22half2_rn(make_float2(((a[2]+b[2])+(c[2]+d[2]))*nd,
                                               ((a[3]+b[3])+(c[3]+d[3]))*nd));
    uint2 o; o.x = *(unsigned*)&r0; o.y = *(unsigned*)&r1;
    ((uint2*)(out + (size_t)node * 64))[lane] = o;
}

// ------- CSR gather (128-dim fp16), HALF-WARP per node, 2-edge pipelined -----
// 16 lanes x uint4 (16B) = 256B row.   (exact R12 form — validated)
__global__ void gather128h_kernel(const __half* __restrict__ x,
                                  __half* __restrict__ out) {
    int gid  = blockIdx.x * blockDim.x + threadIdx.x;
    int node = gid >> 4;
    int lane = gid & 15;
    if (node >= N_NODES) return;
    int lo = g_row[node], hi = g_row[node + 1];
    float a[8] = {0,0,0,0,0,0,0,0};
    float b[8] = {0,0,0,0,0,0,0,0};
    int j = lo;
    for (; j + 1 < hi; j += 2) {
        int s0 = g_csr[j], s1 = g_csr[j + 1];
        uint4 u0 = ((const uint4*)(x + (size_t)s0 * 128))[lane];
        uint4 u1 = ((const uint4*)(x + (size_t)s1 * 128))[lane];
        float2 p0 = __half22float2(*(__half2*)&u0.x);
        float2 p1 = __half22float2(*(__half2*)&u0.y);
        float2 p2 = __half22float2(*(__half2*)&u0.z);
        float2 p3 = __half22float2(*(__half2*)&u0.w);
        float2 q0 = __half22float2(*(__half2*)&u1.x);
        float2 q1 = __half22float2(*(__half2*)&u1.y);
        float2 q2 = __half22float2(*(__half2*)&u1.z);
        float2 q3 = __half22float2(*(__half2*)&u1.w);
        a[0] += p0.x; a[1] += p0.y; a[2] += p1.x; a[3] += p1.y;
        a[4] += p2.x; a[5] += p2.y; a[6] += p3.x; a[7] += p3.y;
        b[0] += q0.x; b[1] += q0.y; b[2] += q1.x; b[3] += q1.y;
        b[4] += q2.x; b[5] += q2.y; b[6] += q3.x; b[7] += q3.y;
    }
    if (j < hi) {
        int s0 = g_csr[j];
        uint4 u0 = ((const uint4*)(x + (size_t)s0 * 128))[lane];
        float2 p0 = __half22float2(*(__half2*)&u0.x);
        float2 p1 = __half22float2(*(__half2*)&u0.y);
        float2 p2 = __half22float2(*(__half2*)&u0.z);
        float2 p3 = __half22float2(*(__half2*)&u0.w);
        a[0] += p0.x; a[1] += p0.y; a[2] += p1.x; a[3] += p1.y;
        a[4] += p2.x; a[5] += p2.y; a[6] += p3.x; a[7] += p3.y;
    }
    float nd = g_norm_dst[node];
    __half2 r0 = __float22half2_rn(make_float2((a[0]+b[0])*nd, (a[1]+b[1])*nd));
    __half2 r1 = __float22half2_rn(make_float2((a[2]+b[2])*nd, (a[3]+b[3])*nd));
    __half2 r2 = __float22half2_rn(make_float2((a[4]+b[4])*nd, (a[5]+b[5])*nd));
    __half2 r3 = __float22half2_rn(make_float2((a[6]+b[6])*nd, (a[7]+b[7])*nd));
    uint4 o;
    o.x = *(unsigned*)&r0; o.y = *(unsigned*)&r1;
    o.z = *(unsigned*)&r2; o.w = *(unsigned*)&r3;
    ((uint4*)(out + (size_t)node * 128))[lane] = o;
}

// final layer gather (64-dim fp16), HALF-WARP per node, 4-edge pipelined ------
__global__ void gather_pool_kernel(const __half* __restrict__ x,
                                   const float* __restrict__ b3,
                                   const void* __restrict__ gid,
                                   float* __restrict__ out) {
    int g_id = blockIdx.x * blockDim.x + threadIdx.x;
    int node = g_id >> 4;
    int lane = g_id & 15;
    if (node >= N_NODES) return;
    int lo = g_row[node], hi = g_row[node + 1];
    float a[4] = {0,0,0,0};
    float b[4] = {0,0,0,0};
    float c[4] = {0,0,0,0};
    float d[4] = {0,0,0,0};
    int j = lo;
    for (; j + 3 < hi; j += 4) {
        int s0 = g_csr[j], s1 = g_csr[j + 1], s2 = g_csr[j + 2], s3 = g_csr[j + 3];
        uint2 u0 = ((const uint2*)(x + (size_t)s0 * 64))[lane];
        uint2 u1 = ((const uint2*)(x + (size_t)s1 * 64))[lane];
        uint2 u2 = ((const uint2*)(x + (size_t)s2 * 64))[lane];
        uint2 u3 = ((const uint2*)(x + (size_t)s3 * 64))[lane];
        float2 p0 = __half22float2(*(__half2*)&u0.x);
        float2 p1 = __half22float2(*(__half2*)&u0.y);
        float2 q0 = __half22float2(*(__half2*)&u1.x);
        float2 q1 = __half22float2(*(__half2*)&u1.y);
        float2 r0 = __half22float2(*(__half2*)&u2.x);
        float2 r1 = __half22float2(*(__half2*)&u2.y);
        float2 t0 = __half22float2(*(__half2*)&u3.x);
        float2 t1 = __half22float2(*(__half2*)&u3.y);
        a[0] += p0.x; a[1] += p0.y; a[2] += p1.x; a[3] += p1.y;
        b[0] += q0.x; b[1] += q0.y; b[2] += q1.x; b[3] += q1.y;
        c[0] += r0.x; c[1] += r0.y; c[2] += r1.x; c[3] += r1.y;
        d[0] += t0.x; d[1] += t0.y; d[2] += t1.x; d[3] += t1.y;
    }
    for (; j < hi; j++) {
        int s0 = g_csr[j];
        uint2 u0 = ((const uint2*)(x + (size_t)s0 * 64))[lane];
        float2 p0 = __half22float2(*(__half2*)&u0.x);
        float2 p1 = __half22float2(*(__half2*)&u0.y);
        a[0] += p0.x; a[1] += p0.y; a[2] += p1.x; a[3] += p1.y;
    }
    float nd = g_norm_dst[node];
    float4 bb = ((const float4*)b3)[lane];
    float r0 = fmaxf(fmaf((a[0]+b[0])+(c[0]+d[0]), nd, bb.x), 0.0f);
    float r1 = fmaxf(fmaf((a[1]+b[1])+(c[1]+d[1]), nd, bb.y), 0.0f);
    float r2 = fmaxf(fmaf((a[2]+b[2])+(c[2]+d[2]), nd, bb.z), 0.0f);
    float r3 = fmaxf(fmaf((a[3]+b[3])+(c[3]+d[3]), nd, bb.w), 0.0f);
    int g = load_idx(gid, node, g_flag_gid);
    float* o = out + (size_t)g * 64 + lane * 4;
    atomicAdd(o + 0, r0);
    atomicAdd(o + 1, r1);
    atomicAdd(o + 2, r2);
    atomicAdd(o + 3, r3);
}

// ------- tensor-core GEMM with smem-staged A tile ----------------------------
// A: [N_NODES, DIN] fp16 row-major.  Bh: [DIN, DOUT] fp16 row-major.
// M_TILE=80, warps = DOUT/16, each warp owns one 16-col n_tile and 5 m-frags.
// EPI==1: v = relu(acc + bias[col]) * norm_src[row];  EPI==0: v = acc.
template <int DIN, int DOUT, int EPI>
__global__ void wmma_gemm_kernel(const __half* __restrict__ A,
                                 const __half* __restrict__ Bh,
                                 const float* __restrict__ bias,
                                 __half* __restrict__ out) {
    constexpr int M_TILE  = 80;
    constexpr int NWARPS  = DOUT / 16;
    constexpr int THREADS = NWARPS * 32;
    constexpr int MF      = M_TILE / 16;    // 5 m-fragments per warp
    __shared__ __half As[M_TILE * DIN];
    __shared__ float scratch[NWARPS][16 * 16];
    int tid  = threadIdx.x;
    int w    = tid >> 5;
    int lane = tid & 31;
    size_t base = (size_t)blockIdx.x * M_TILE;

    // cooperative 16B-vector load of the A tile
    {
        const uint4* srcv = (const uint4*)(A + base * DIN);
        uint4* dstv = (uint4*)As;
#pragma unroll
        for (int i = tid; i < M_TILE * DIN / 8; i += THREADS) dstv[i] = srcv[i];
    }
    __syncthreads();

    wmma::fragment<wmma::accumulator, 16, 16, 16, float> acc[MF];
#pragma unroll
    for (int m = 0; m < MF; m++) wmma::fill_fragment(acc[m], 0.0f);

    wmma::fragment<wmma::matrix_a, 16, 16, 16, __half, wmma::row_major> afrag;
    wmma::fragment<wmma::matrix_b, 16, 16, 16, __half, wmma::row_major> bfrag;

#pragma unroll
    for (int k = 0; k < DIN / 16; k++) {
        wmma::load_matrix_sync(bfrag, Bh + (size_t)(k * 16) * DOUT + w * 16, DOUT);
#pragma unroll
        for (int m = 0; m < MF; m++) {
            wmma::load_matrix_sync(afrag, As + (size_t)(m * 16) * DIN + k * 16, DIN);
            wmma::mma_sync(acc[m], afrag, bfrag, acc[m]);
        }
    }

#pragma unroll
    for (int m = 0; m < MF; m++) {
        wmma::store_matrix_sync(scratch[w], acc[m], 16, wmma::mem_row_major);
        __syncwarp();
#pragma unroll
        for (int e = lane; e < 256; e += 32) {
            int r = e >> 4, c = e & 15;
            size_t row = base + (size_t)m * 16 + r;
            int col = w * 16 + c;
            float v = scratch[w][e];
            if (EPI) v = fmaxf(v + bias[col], 0.0f) * g_norm_src[row];
            out[row * DOUT + col] = __float2half_rn(v);
        }
        __syncwarp();
    }
}

// ---------------- launch ------------------------------------------------------
extern "C" void kernel_launch(void* const* d_in, const int* in_sizes, int n_in,
                              void* d_out, int out_size) {
    const float* h        = (const float*)d_in[0];
    const void*  src      = d_in[1];
    const void*  dst      = d_in[2];
    const void*  graph_id = d_in[3];
    const float* W1 = (const float*)d_in[4];
    const float* b1 = (const float*)d_in[5];
    const float* W2 = (const float*)d_in[6];
    const float* b2 = (const float*)d_in[7];
    const float* W3 = (const float*)d_in[8];
    const float* b3 = (const float*)d_in[9];
    float* out = (float*)d_out;

    __half *pA, *pB, *pW1, *pW2, *pW3;
    cudaGetSymbolAddress((void**)&pA,  g_hA);
    cudaGetSymbolAddress((void**)&pB,  g_hB);
    cudaGetSymbolAddress((void**)&pW1, g_w1h);
    cudaGetSymbolAddress((void**)&pW2, g_w2h);
    cudaGetSymbolAddress((void**)&pW3, g_w3h);

    // setup: init (+detect, +zero out), degrees, 2-stage scan, CSR fill, W->fp16
    init_kernel<<<(N_NODES + 255) / 256, 256>>>((const unsigned*)src,
                                                (const unsigned*)graph_id, out);
    deg_kernel<<<2048, 256>>>(src, dst);
    scanA_kernel<<<SCAN_BLOCKS, 1024>>>();
    scanB_kernel<<<SCAN_BLOCKS, 1024>>>();
    fill_csr_kernel<<<2048, 256>>>(src, dst);
    wconv_kernel<<<(128 * 128 + 255) / 256, 256>>>(W1, W2, W3);

    const int HW_GRID = (N_NODES * 16 + 255) / 256;   // half-warp per node

    // layer 1: prescale(h)->A(64), gather64 A->B(64), wmma 64->128 B->A
    prescale_kernel<<<(N_NODES * 32 + 255) / 256, 256>>>(h);
    gather64h_kernel<<<HW_GRID, 256>>>(pA, pB);
    wmma_gemm_kernel<64, 128, 1><<<N_NODES / 80, 256>>>(pB, pW1, b1, pA);

    // layer 2: gather128 A->B, wmma 128->128 B->A
    gather128h_kernel<<<HW_GRID, 256>>>(pA, pB);
    wmma_gemm_kernel<128, 128, 1><<<N_NODES / 80, 256>>>(pB, pW2, b2, pA);

    // layer 3: transform first (wmma 128->64, no epi) A->B, then gather+pool
    wmma_gemm_kernel<128, 64, 0><<<N_NODES / 80, 128>>>(pA, pW3, nullptr, pB);
    gather_pool_kernel<<<HW_GRID, 256>>>(pB, b3, graph_id, out);
}

// round 16
// speedup vs baseline: 1.1498x; 1.0748x over previous
#include <cuda_runtime.h>
#include <cuda_fp16.h>
#include <mma.h>
#include <stdint.h>

using namespace nvcuda;

#define N_NODES 100000
#define N_EDGES 1600000
#define N_GRAPHS 256
#define SCAN_BLOCKS 100
#define SCAN_CHUNK 1000   // N_NODES = SCAN_BLOCKS * SCAN_CHUNK exactly

// ---------------- scratch (no allocation allowed -> device globals) ----------
__device__ int    g_deg_out[N_NODES];
__device__ int    g_deg_in[N_NODES];
__device__ float  g_norm_src[N_NODES];
__device__ float  g_norm_dst[N_NODES];
__device__ int    g_row[N_NODES + 1];           // CSR row offsets (by dst)
__device__ int    g_cur[N_NODES];               // fill cursors
__device__ int    g_csr[N_EDGES];               // src index per CSR slot
__device__ int    g_blk[SCAN_BLOCKS];           // per-block degree sums
__device__ __half g_hA[(size_t)N_NODES * 128];  // fp16 feature buffer A
__device__ __half g_hB[(size_t)N_NODES * 128];  // fp16 feature buffer B
__device__ __half g_w1h[64 * 128];              // fp16 weights
__device__ __half g_w2h[128 * 128];
__device__ __half g_w3h[128 * 64];
__device__ int    g_flag_idx;                   // 1 = src/dst are int32
__device__ int    g_flag_gid;                   // 1 = graph_id is int32

// ---------------- helpers ----------------------------------------------------
__device__ __forceinline__ int load_idx(const void* p, long long i, int is32) {
    if (is32) return ((const int*)p)[i];
    return (int)(((const long long*)p)[i]);
}

// init: zero degrees + output, convert weights to fp16; block 0 also does
// dtype detection.
// int64 values < 2^31 -> every odd 32-bit word is 0; int32 data -> nonzero.
// src: head window (random values => certain nonzero if int32).
// gid: TAIL window (sorted ascending; head is legitimately zero either way).
__global__ void init_kernel(const unsigned* __restrict__ s,
                            const unsigned* __restrict__ g,
                            float* __restrict__ out,
                            const float* __restrict__ W1,
                            const float* __restrict__ W2,
                            const float* __restrict__ W3) {
    int i = blockIdx.x * blockDim.x + threadIdx.x;
    if (i == 0) { g_flag_idx = 0; g_flag_gid = 0; }
    if (i < N_NODES) { g_deg_out[i] = 0; g_deg_in[i] = 0; }
    if (i < N_GRAPHS * 64) out[i] = 0.0f;
    if (i < 64 * 128)  g_w1h[i] = __float2half_rn(W1[i]);
    if (i < 128 * 128) g_w2h[i] = __float2half_rn(W2[i]);
    if (i < 128 * 64)  g_w3h[i] = __float2half_rn(W3[i]);
    if (blockIdx.x == 0) {
        int fi = 0, fg = 0;
        for (int j = threadIdx.x; j < 2048; j += 256)
            if ((j & 1) && s[j]) fi = 1;
        for (int j = N_NODES - 2048 + threadIdx.x; j < N_NODES; j += 256)
            if ((j & 1) && g[j]) fg = 1;
        if (fi) g_flag_idx = 1;
        if (fg) g_flag_gid = 1;
    }
}

// ---------------- degrees ----------------------------------------------------
__global__ void deg_kernel(const void* src, const void* dst) {
    int is32 = g_flag_idx;
    long long i = (long long)blockIdx.x * blockDim.x + threadIdx.x;
    long long stride = (long long)gridDim.x * blockDim.x;
    for (; i < N_EDGES; i += stride) {
        atomicAdd(&g_deg_out[load_idx(src, i, is32)], 1);
        atomicAdd(&g_deg_in[load_idx(dst, i, is32)], 1);
    }
}

// scan stage A: per-block degree sums + norms (SCAN_BLOCKS blocks, 1024 thr)
__global__ void scanA_kernel() {
    __shared__ int ssum[1024];
    int b = blockIdx.x;
    int t = threadIdx.x;
    int i = b * SCAN_CHUNK + t;
    int d = 0;
    if (t < SCAN_CHUNK) {
        d = g_deg_in[i];
        int doo = g_deg_out[i];
        g_norm_src[i] = (doo > 0) ? rsqrtf((float)doo) : 0.0f;
        g_norm_dst[i] = (d   > 0) ? rsqrtf((float)d)   : 0.0f;
    }
    ssum[t] = d;
    __syncthreads();
    for (int off = 512; off > 0; off >>= 1) {
        if (t < off) ssum[t] += ssum[t + off];
        __syncthreads();
    }
    if (t == 0) g_blk[b] = ssum[0];
}

// scan stage B: every block scans the 100 partials + its local 1000 elements
__global__ void scanB_kernel() {
    __shared__ int sblk[128];
    __shared__ int sdeg[1024];
    int b = blockIdx.x;
    int t = threadIdx.x;

    if (t < 128) sblk[t] = (t < SCAN_BLOCKS) ? g_blk[t] : 0;
    __syncthreads();
    for (int off = 1; off < 128; off <<= 1) {
        int v = (t >= off && t < 128) ? sblk[t - off] : 0;
        __syncthreads();
        if (t < 128) sblk[t] += v;
        __syncthreads();
    }
    int blk_off = (b > 0) ? sblk[b - 1] : 0;

    int i = b * SCAN_CHUNK + t;
    int d = (t < SCAN_CHUNK) ? g_deg_in[i] : 0;
    sdeg[t] = d;
    __syncthreads();
    for (int off = 1; off < 1024; off <<= 1) {
        int v = (t >= off) ? sdeg[t - off] : 0;
        __syncthreads();
        sdeg[t] += v;
        __syncthreads();
    }
    if (t < SCAN_CHUNK) {
        int excl = blk_off + sdeg[t] - d;
        g_row[i] = excl;
        g_cur[i] = excl;
        if (b == SCAN_BLOCKS - 1 && t == SCAN_CHUNK - 1)
            g_row[N_NODES] = blk_off + sdeg[t];
    }
}

__global__ void fill_csr_kernel(const void* src, const void* dst) {
    int is32 = g_flag_idx;
    long long i = (long long)blockIdx.x * blockDim.x + threadIdx.x;
    long long stride = (long long)gridDim.x * blockDim.x;
    for (; i < N_EDGES; i += stride) {
        int d = load_idx(dst, i, is32);
        int pos = atomicAdd(&g_cur[d], 1);
        g_csr[pos] = load_idx(src, i, is32);
    }
}

// ------ prescale: g_hA = fp16(h * norm_src), row-major 64/node ---------------
__global__ void prescale_kernel(const float* __restrict__ h) {
    int i = blockIdx.x * blockDim.x + threadIdx.x;   // over N_NODES*32 half2
    if (i >= N_NODES * 32) return;
    int n = i >> 5;
    float ns = g_norm_src[n];
    float2 v = ((const float2*)h)[i];
    v.x *= ns; v.y *= ns;
    ((__half2*)g_hA)[i] = __float22half2_rn(v);
}

// ------- CSR gather (64-dim fp16), HALF-WARP per node, 2-edge pipelined ------
// 16 lanes x uint2 (8B) = 128B row; 2 nodes per warp concurrently.
__global__ void gather64h_kernel(const __half* __restrict__ x,
                                 __half* __restrict__ out) {
    int gid  = blockIdx.x * blockDim.x + threadIdx.x;
    int node = gid >> 4;
    int lane = gid & 15;
    if (node >= N_NODES) return;
    int lo = g_row[node], hi = g_row[node + 1];
    float a0=0.f,a1=0.f,a2=0.f,a3=0.f,b0=0.f,b1=0.f,b2=0.f,b3=0.f;
    int j = lo;
    for (; j + 1 < hi; j += 2) {
        int s0 = g_csr[j], s1 = g_csr[j + 1];
        uint2 u0 = ((const uint2*)(x + (size_t)s0 * 64))[lane];
        uint2 u1 = ((const uint2*)(x + (size_t)s1 * 64))[lane];
        float2 p0 = __half22float2(*(__half2*)&u0.x);
        float2 p1 = __half22float2(*(__half2*)&u0.y);
        float2 q0 = __half22float2(*(__half2*)&u1.x);
        float2 q1 = __half22float2(*(__half2*)&u1.y);
        a0 += p0.x; a1 += p0.y; a2 += p1.x; a3 += p1.y;
        b0 += q0.x; b1 += q0.y; b2 += q1.x; b3 += q1.y;
    }
    if (j < hi) {
        int s0 = g_csr[j];
        uint2 u0 = ((const uint2*)(x + (size_t)s0 * 64))[lane];
        float2 p0 = __half22float2(*(__half2*)&u0.x);
        float2 p1 = __half22float2(*(__half2*)&u0.y);
        a0 += p0.x; a1 += p0.y; a2 += p1.x; a3 += p1.y;
    }
    float nd = g_norm_dst[node];
    __half2 r0 = __float22half2_rn(make_float2((a0 + b0) * nd, (a1 + b1) * nd));
    __half2 r1 = __float22half2_rn(make_float2((a2 + b2) * nd, (a3 + b3) * nd));
    uint2 o; o.x = *(unsigned*)&r0; o.y = *(unsigned*)&r1;
    ((uint2*)(out + (size_t)node * 64))[lane] = o;
}

// ------- CSR gather (128-dim fp16), HALF-WARP per node, 2-edge pipelined -----
// 16 lanes x uint4 (16B) = 256B row.
__global__ void gather128h_kernel(const __half* __restrict__ x,
                                  __half* __restrict__ out) {
    int gid  = blockIdx.x * blockDim.x + threadIdx.x;
    int node = gid >> 4;
    int lane = gid & 15;
    if (node >= N_NODES) return;
    int lo = g_row[node], hi = g_row[node + 1];
    float a[8] = {0,0,0,0,0,0,0,0};
    float b[8] = {0,0,0,0,0,0,0,0};
    int j = lo;
    for (; j + 1 < hi; j += 2) {
        int s0 = g_csr[j], s1 = g_csr[j + 1];
        uint4 u0 = ((const uint4*)(x + (size_t)s0 * 128))[lane];
        uint4 u1 = ((const uint4*)(x + (size_t)s1 * 128))[lane];
        float2 p0 = __half22float2(*(__half2*)&u0.x);
        float2 p1 = __half22float2(*(__half2*)&u0.y);
        float2 p2 = __half22float2(*(__half2*)&u0.z);
        float2 p3 = __half22float2(*(__half2*)&u0.w);
        float2 q0 = __half22float2(*(__half2*)&u1.x);
        float2 q1 = __half22float2(*(__half2*)&u1.y);
        float2 q2 = __half22float2(*(__half2*)&u1.z);
        float2 q3 = __half22float2(*(__half2*)&u1.w);
        a[0] += p0.x; a[1] += p0.y; a[2] += p1.x; a[3] += p1.y;
        a[4] += p2.x; a[5] += p2.y; a[6] += p3.x; a[7] += p3.y;
        b[0] += q0.x; b[1] += q0.y; b[2] += q1.x; b[3] += q1.y;
        b[4] += q2.x; b[5] += q2.y; b[6] += q3.x; b[7] += q3.y;
    }
    if (j < hi) {
        int s0 = g_csr[j];
        uint4 u0 = ((const uint4*)(x + (size_t)s0 * 128))[lane];
        float2 p0 = __half22float2(*(__half2*)&u0.x);
        float2 p1 = __half22float2(*(__half2*)&u0.y);
        float2 p2 = __half22float2(*(__half2*)&u0.z);
        float2 p3 = __half22float2(*(__half2*)&u0.w);
        a[0] += p0.x; a[1] += p0.y; a[2] += p1.x; a[3] += p1.y;
        a[4] += p2.x; a[5] += p2.y; a[6] += p3.x; a[7] += p3.y;
    }
    float nd = g_norm_dst[node];
    __half2 r0 = __float22half2_rn(make_float2((a[0]+b[0])*nd, (a[1]+b[1])*nd));
    __half2 r1 = __float22half2_rn(make_float2((a[2]+b[2])*nd, (a[3]+b[3])*nd));
    __half2 r2 = __float22half2_rn(make_float2((a[4]+b[4])*nd, (a[5]+b[5])*nd));
    __half2 r3 = __float22half2_rn(make_float2((a[6]+b[6])*nd, (a[7]+b[7])*nd));
    uint4 o;
    o.x = *(unsigned*)&r0; o.y = *(unsigned*)&r1;
    o.z = *(unsigned*)&r2; o.w = *(unsigned*)&r3;
    ((uint4*)(out + (size_t)node * 128))[lane] = o;
}

// final layer gather (64-dim fp16), HALF-WARP per node, pooled atomicAdd ------
__global__ void gather_pool_kernel(const __half* __restrict__ x,
                                   const float* __restrict__ b3,
                                   const void* __restrict__ gid,
                                   float* __restrict__ out) {
    int g_id = blockIdx.x * blockDim.x + threadIdx.x;
    int node = g_id >> 4;
    int lane = g_id & 15;
    if (node >= N_NODES) return;
    int lo = g_row[node], hi = g_row[node + 1];
    float a0=0.f,a1=0.f,a2=0.f,a3=0.f,b0=0.f,b1=0.f,b2=0.f,b3v=0.f;
    int j = lo;
    for (; j + 1 < hi; j += 2) {
        int s0 = g_csr[j], s1 = g_csr[j + 1];
        uint2 u0 = ((const uint2*)(x + (size_t)s0 * 64))[lane];
        uint2 u1 = ((const uint2*)(x + (size_t)s1 * 64))[lane];
        float2 p0 = __half22float2(*(__half2*)&u0.x);
        float2 p1 = __half22float2(*(__half2*)&u0.y);
        float2 q0 = __half22float2(*(__half2*)&u1.x);
        float2 q1 = __half22float2(*(__half2*)&u1.y);
        a0 += p0.x; a1 += p0.y; a2 += p1.x; a3 += p1.y;
        b0 += q0.x; b1 += q0.y; b2 += q1.x; b3v += q1.y;
    }
    if (j < hi) {
        int s0 = g_csr[j];
        uint2 u0 = ((const uint2*)(x + (size_t)s0 * 64))[lane];
        float2 p0 = __half22float2(*(__half2*)&u0.x);
        float2 p1 = __half22float2(*(__half2*)&u0.y);
        a0 += p0.x; a1 += p0.y; a2 += p1.x; a3 += p1.y;
    }
    float nd = g_norm_dst[node];
    float4 bb = ((const float4*)b3)[lane];
    float r0 = fmaxf(fmaf(a0 + b0,  nd, bb.x), 0.0f);
    float r1 = fmaxf(fmaf(a1 + b1,  nd, bb.y), 0.0f);
    float r2 = fmaxf(fmaf(a2 + b2,  nd, bb.z), 0.0f);
    float r3 = fmaxf(fmaf(a3 + b3v, nd, bb.w), 0.0f);
    int g = load_idx(gid, node, g_flag_gid);
    float* o = out + (size_t)g * 64 + lane * 4;
    atomicAdd(o + 0, r0);
    atomicAdd(o + 1, r1);
    atomicAdd(o + 2, r2);
    atomicAdd(o + 3, r3);
}

// ------- tensor-core GEMM with smem-staged A tile ----------------------------
// A: [N_NODES, DIN] fp16 row-major.  Bh: [DIN, DOUT] fp16 row-major.
// M_TILE=80, warps = DOUT/16, each warp owns one 16-col n_tile and 5 m-frags.
// EPI==1: v = relu(acc + bias[col]) * norm_src[row];  EPI==0: v = acc.
template <int DIN, int DOUT, int EPI>
__global__ void wmma_gemm_kernel(const __half* __restrict__ A,
                                 const __half* __restrict__ Bh,
                                 const float* __restrict__ bias,
                                 __half* __restrict__ out) {
    constexpr int M_TILE  = 80;
    constexpr int NWARPS  = DOUT / 16;
    constexpr int THREADS = NWARPS * 32;
    constexpr int MF      = M_TILE / 16;    // 5 m-fragments per warp
    __shared__ __half As[M_TILE * DIN];
    __shared__ float scratch[NWARPS][16 * 16];
    int tid  = threadIdx.x;
    int w    = tid >> 5;
    int lane = tid & 31;
    size_t base = (size_t)blockIdx.x * M_TILE;

    // cooperative 16B-vector load of the A tile
    {
        const uint4* srcv = (const uint4*)(A + base * DIN);
        uint4* dstv = (uint4*)As;
#pragma unroll
        for (int i = tid; i < M_TILE * DIN / 8; i += THREADS) dstv[i] = srcv[i];
    }
    __syncthreads();

    wmma::fragment<wmma::accumulator, 16, 16, 16, float> acc[MF];
#pragma unroll
    for (int m = 0; m < MF; m++) wmma::fill_fragment(acc[m], 0.0f);

    wmma::fragment<wmma::matrix_a, 16, 16, 16, __half, wmma::row_major> afrag;
    wmma::fragment<wmma::matrix_b, 16, 16, 16, __half, wmma::row_major> bfrag;

#pragma unroll
    for (int k = 0; k < DIN / 16; k++) {
        wmma::load_matrix_sync(bfrag, Bh + (size_t)(k * 16) * DOUT + w * 16, DOUT);
#pragma unroll
        for (int m = 0; m < MF; m++) {
            wmma::load_matrix_sync(afrag, As + (size_t)(m * 16) * DIN + k * 16, DIN);
            wmma::mma_sync(acc[m], afrag, bfrag, acc[m]);
        }
    }

#pragma unroll
    for (int m = 0; m < MF; m++) {
        wmma::store_matrix_sync(scratch[w], acc[m], 16, wmma::mem_row_major);
        __syncwarp();
#pragma unroll
        for (int e = lane; e < 256; e += 32) {
            int r = e >> 4, c = e & 15;
            size_t row = base + (size_t)m * 16 + r;
            int col = w * 16 + c;
            float v = scratch[w][e];
            if (EPI) v = fmaxf(v + bias[col], 0.0f) * g_norm_src[row];
            out[row * DOUT + col] = __float2half_rn(v);
        }
        __syncwarp();
    }
}

// ---------------- launch ------------------------------------------------------
extern "C" void kernel_launch(void* const* d_in, const int* in_sizes, int n_in,
                              void* d_out, int out_size) {
    const float* h        = (const float*)d_in[0];
    const void*  src      = d_in[1];
    const void*  dst      = d_in[2];
    const void*  graph_id = d_in[3];
    const float* W1 = (const float*)d_in[4];
    const float* b1 = (const float*)d_in[5];
    const float* W2 = (const float*)d_in[6];
    const float* b2 = (const float*)d_in[7];
    const float* W3 = (const float*)d_in[8];
    const float* b3 = (const float*)d_in[9];
    float* out = (float*)d_out;

    __half *pA, *pB, *pW1, *pW2, *pW3;
    cudaGetSymbolAddress((void**)&pA,  g_hA);
    cudaGetSymbolAddress((void**)&pB,  g_hB);
    cudaGetSymbolAddress((void**)&pW1, g_w1h);
    cudaGetSymbolAddress((void**)&pW2, g_w2h);
    cudaGetSymbolAddress((void**)&pW3, g_w3h);

    // setup: init (+detect, +zero out, +W->fp16), degrees, 2-stage scan, CSR fill
    init_kernel<<<(N_NODES + 255) / 256, 256>>>((const unsigned*)src,
                                                (const unsigned*)graph_id,
                                                out, W1, W2, W3);
    deg_kernel<<<2048, 256>>>(src, dst);
    scanA_kernel<<<SCAN_BLOCKS, 1024>>>();
    scanB_kernel<<<SCAN_BLOCKS, 1024>>>();
    fill_csr_kernel<<<2048, 256>>>(src, dst);

    const int HW_GRID = (N_NODES * 16 + 255) / 256;   // half-warp per node

    // layer 1: prescale(h)->A(64), gather64 A->B(64), wmma 64->128 B->A
    prescale_kernel<<<(N_NODES * 32 + 255) / 256, 256>>>(h);
    gather64h_kernel<<<HW_GRID, 256>>>(pA, pB);
    wmma_gemm_kernel<64, 128, 1><<<N_NODES / 80, 256>>>(pB, pW1, b1, pA);

    // layer 2: gather128 A->B, wmma 128->128 B->A
    gather128h_kernel<<<HW_GRID, 256>>>(pA, pB);
    wmma_gemm_kernel<128, 128, 1><<<N_NODES / 80, 256>>>(pB, pW2, b2, pA);

    // layer 3: transform first (wmma 128->64, no epi) A->B, then gather+pool
    wmma_gemm_kernel<128, 64, 0><<<N_NODES / 80, 128>>>(pA, pW3, nullptr, pB);
    gather_pool_kernel<<<HW_GRID, 256>>>(pB, b3, graph_id, out);
}